// round 9
// baseline (speedup 1.0000x reference)
#include <cuda_runtime.h>
#include <cuda_fp16.h>

typedef unsigned long long ull;

#define HN 512
#define KN 64
#define NSAMP 16384
#define LRATE 0.001f
#define EPSF 1e-8f
#define WARPS 8
#define CHK 64
#define NCHUNK (HN/CHK)
#define ROWB 272                      // bytes per staged row (68 half2); 68%32==4 -> conflict-free
#define FBUF_B (CHK*ROWB)             // 17408 bytes per F buffer

// smem layout (float units)
#define FS_FLOATS   (2*FBUF_B/4)      // 8704 (double-buffered fp16 F chunks)
#define CS_OFF      FS_FLOATS
#define CS_WARP     576               // 16 quads * 36 floats (A at +0, B at +16, pad)
#define GB_OFF      (CS_OFF + WARPS*CS_WARP)
#define GB_WARP     768
#define WV_OFF      (GB_OFF + WARPS*GB_WARP)
#define SMEM_FLOATS (WV_OFF + WARPS*384)
#define SMEM_BYTES  (SMEM_FLOATS*4)   // 90112 B -> 2 CTAs/SM

__device__ __align__(16) unsigned g_Fh[HN*KN];        // [h][k] = half2(Bd, Bdd)
__device__ __align__(16) float4 g_PT4[(HN/2)*KN];     // [hp][k] = (pinv[k][2hp], B[2hp][k], pinv[k][2hp+1], B[2hp+1][k])
__device__ __align__(16) float2 g_Mp[KN*32];          // [kk*32+l] = (M[kk][l], M[kk][l+32])

// ---- packed f32x2 helpers ----
__device__ __forceinline__ ull ffma2(ull a, ull b, ull c){
    ull d; asm("fma.rn.f32x2 %0,%1,%2,%3;" : "=l"(d) : "l"(a), "l"(b), "l"(c)); return d;
}
__device__ __forceinline__ void funpack(ull u, float& x, float& y){
    asm("mov.b64 {%0,%1},%2;" : "=f"(x), "=f"(y) : "l"(u));
}
__device__ __forceinline__ ull fdup(float x){
    ull r; asm("mov.b64 %0,{%1,%1};" : "=l"(r) : "f"(x)); return r;
}
__device__ __forceinline__ ull pack2(float lo, float hi){
    ull r; asm("mov.b64 %0,{%1,%2};" : "=l"(r) : "f"(lo), "f"(hi)); return r;
}
// half2 bits -> packed f32x2
__device__ __forceinline__ ull h2f2(unsigned u){
    __half2 h = *(__half2*)&u;
    float2 f = __half22float2(h);
    return pack2(f.x, f.y);
}
// rsqrt on the fma/alu pipes: bit-hack seed + 2 Newton iterations (~4e-6 rel err)
__device__ __forceinline__ float rsqrt_fma(float x){
    float y = __uint_as_float(0x5f3759dfu - (__float_as_uint(x) >> 1));
    y = y * (1.5f - 0.5f*x*y*y);
    y = y * (1.5f - 0.5f*x*y*y);
    return y;
}
// async 16B global->shared copy (LDGSTS), no data registers
__device__ __forceinline__ void cpasync16(void* smem_dst, const void* gsrc){
    unsigned s = (unsigned)__cvta_generic_to_shared(smem_dst);
    asm volatile("cp.async.cg.shared.global [%0], [%1], 16;" :: "r"(s), "l"(gsrc));
}
#define CPASYNC_COMMIT() asm volatile("cp.async.commit_group;")
#define CPASYNC_WAIT0()  asm volatile("cp.async.wait_group 0;")

// K1: prep (blocks 0..127) + gram (blocks 128..191)
__global__ void prep_kernel(const float* __restrict__ B,
                            const float* __restrict__ Bd,
                            const float* __restrict__ Bdd,
                            const float* __restrict__ Bddd,
                            const float* __restrict__ Bpinv,
                            const float* __restrict__ lambdas)
{
    int bid = blockIdx.x, t = threadIdx.x;
    if (bid < 128) {
        int idx = bid*256 + t;
        __half2 hv = __halves2half2(__float2half(Bd[idx]), __float2half(Bdd[idx]));
        g_Fh[idx] = *(unsigned*)&hv;
        if (idx < (HN/2)*KN) {
            int hp = idx >> 6, k = idx & 63;
            int h0 = 2*hp, h1 = 2*hp + 1;
            g_PT4[idx] = make_float4(Bpinv[k*HN + h0], B[h0*KN + k],
                                     Bpinv[k*HN + h1], B[h1*KN + k]);
        }
    } else {
        __shared__ float pab[4][KN], paj[4][KN], Mrow[KN];
        int kk = bid - 128;
        int k2 = t & 63, part = t >> 6;
        float ab = 0.f, aj = 0.f;
        for (int h = part*128; h < part*128 + 128; h++) {
            ab += B[h*KN + kk]    * B[h*KN + k2];
            aj += Bddd[h*KN + kk] * Bddd[h*KN + k2];
        }
        pab[part][k2] = ab; paj[part][k2] = aj;
        __syncthreads();
        if (t < KN) {
            float sab = pab[0][t]+pab[1][t]+pab[2][t]+pab[3][t];
            float saj = paj[0][t]+paj[1][t]+paj[2][t]+paj[3][t];
            Mrow[t] = 2.f * (lambdas[0]*sab + lambdas[2]*saj);
        }
        __syncthreads();
        if (t < 32) g_Mp[kk*32 + t] = make_float2(Mrow[t], Mrow[t+32]);
    }
}

// Elementwise gradient of the power-law term wrt V and A (includes l2).
__device__ __forceinline__ void elemgrad(
    float v0, float v1, float v2,
    float a0, float a1, float a2,
    float aa, float bb, float l2, float* g)
{
    float vsq = v0*v0 + v1*v1 + v2*v2;
    float inv_vn = vsq > 0.f ? rsqrt_fma(vsq) : 0.f;
    float vn  = vsq * inv_vn;
    float vne = vn + EPSF;

    float cx = v1*a2 - v2*a1;
    float cy = v2*a0 - v0*a2;
    float cz = v0*a1 - v1*a0;
    float csq = cx*cx + cy*cy + cz*cz;
    float inv_cn = csq > 0.f ? rsqrtf(csq) : 0.f;
    float cn = csq * inv_cn;

    float inv_den = inv_vn * inv_vn * inv_vn;
    float kappa = cn * inv_den;

    float ks  = fminf(fmaxf(kappa, 1e-4f), 1e4f);
    float lpr = bb * __logf(ks);
    float lp  = fminf(fmaxf(lpr, -10.f), 10.f);
    float traw   = aa * __expf(lp);
    float target = fminf(fmaxf(traw, 1e-6f), 1e6f);

    float u   = vn - target;
    float gvn = 2.f * l2 * u;
    float gt  = (traw > 1e-6f && traw < 1e6f) ? (-2.f * l2 * u) : 0.f;
    float glk = ((lpr > -10.f && lpr < 10.f) ? gt * traw : 0.f) * bb;
    float gk  = (kappa > 1e-4f && kappa < 1e4f) ? glk : 0.f;
    float gcn  = gk * inv_cn;
    float gden = -gk * inv_den;
    gvn += gden * 3.f * vne * vne;

    float scr = gcn * inv_cn;
    float gc0 = scr * cx, gc1 = scr * cy, gc2 = scr * cz;
    float sV = gvn * inv_vn;
    g[0] = sV*v0 + a1*gc2 - a2*gc1;
    g[1] = sV*v1 + a2*gc0 - a0*gc2;
    g[2] = sV*v2 + a0*gc1 - a1*gc0;
    g[3] = gc1*v2 - gc2*v1;
    g[4] = gc2*v0 - gc0*v2;
    g[5] = gc0*v1 - gc1*v0;
}

// K2: main. One warp = 2 samples; cp.async double-buffered F staging,
// one block barrier per chunk, staging overlapped with compute.
__global__ __launch_bounds__(256, 2)
void inner_opt_kernel(const float* __restrict__ R_U,
                      const float* __restrict__ alpha,
                      const float* __restrict__ beta,
                      const float* __restrict__ lambdas,
                      float* __restrict__ out)
{
    extern __shared__ __align__(16) float smem[];
    char* FhBase = (char*)smem;                             // 2 buffers of [CHK][272 B]
    const int w = threadIdx.x >> 5;
    const int l = threadIdx.x & 31;
    float* Cq  = smem + CS_OFF + w*CS_WARP;                 // [quad][36]: A 12f @+0, B 12f @+16
    float2* GwA = (float2*)(smem + GB_OFF + w*GB_WARP);     // [j][h] (gV,gA)
    float2* GwB = GwA + 192;
    float*  Ws  = smem + WV_OFF + w*384;                    // [lane][12] -wv stash

    const int sA = blockIdx.x * (WARPS*2) + w*2;
    const int sB = sA + 1;
    const int k0 = l, k1 = l + 32;
    const int qa = l >> 2, la3 = (l & 3) * 3;               // C slot coords for k0 (k1: quad+8)

    const float l1 = lambdas[0], l2 = lambdas[1];
    const float aaA = alpha[sA], bbA = beta[sA];
    const float aaB = alpha[sB], bbB = beta[sB];

    float c[2][2][3];   // [sample][k-half][j] kept in registers across all steps

    // ---- prologue: async-stage chunk 0 into buffer 0 (overlaps init below) ----
    {
        const char* srcb = (const char*)g_Fh;
        int t = threadIdx.x;
        #pragma unroll
        for (int i = 0; i < 4; i++) {
            int idx = t + 256*i;
            int h = idx >> 4, q = idx & 15;
            cpasync16(FhBase + h*ROWB + q*16, srcb + idx*16);
        }
        CPASYNC_COMMIT();
    }

    // ---- init: (c, wv_raw) pair-packed over coalesced PT4 ----
    {
        ull accw[2][2][3] = {{{0,0,0},{0,0,0}},{{0,0,0},{0,0,0}}};
        const float4* rpA = (const float4*)(R_U + (size_t)sA * (HN*3));
        const float4* rpB = (const float4*)(R_U + (size_t)sB * (HN*3));
        #pragma unroll 1
        for (int q = 0; q < HN/4; q++) {
            ulonglong2 u00 = *(const ulonglong2*)&g_PT4[(2*q  )*KN + l];
            ulonglong2 u01 = *(const ulonglong2*)&g_PT4[(2*q  )*KN + l + 32];
            ulonglong2 u10 = *(const ulonglong2*)&g_PT4[(2*q+1)*KN + l];
            ulonglong2 u11 = *(const ulonglong2*)&g_PT4[(2*q+1)*KN + l + 32];
            #pragma unroll
            for (int s = 0; s < 2; s++) {
                const float4* rp = s ? rpB : rpA;
                float4 r0 = rp[3*q], r1 = rp[3*q+1], r2 = rp[3*q+2];
                float rr[12] = {r0.x,r0.y,r0.z,r0.w, r1.x,r1.y,r1.z,r1.w, r2.x,r2.y,r2.z,r2.w};
                #pragma unroll
                for (int j = 0; j < 3; j++) {
                    ull d0 = fdup(rr[j]);
                    ull d1 = fdup(rr[3+j]);
                    ull d2 = fdup(rr[6+j]);
                    ull d3 = fdup(rr[9+j]);
                    accw[s][0][j] = ffma2(u00.x, d0, accw[s][0][j]);
                    accw[s][0][j] = ffma2(u00.y, d1, accw[s][0][j]);
                    accw[s][0][j] = ffma2(u10.x, d2, accw[s][0][j]);
                    accw[s][0][j] = ffma2(u10.y, d3, accw[s][0][j]);
                    accw[s][1][j] = ffma2(u01.x, d0, accw[s][1][j]);
                    accw[s][1][j] = ffma2(u01.y, d1, accw[s][1][j]);
                    accw[s][1][j] = ffma2(u11.x, d2, accw[s][1][j]);
                    accw[s][1][j] = ffma2(u11.y, d3, accw[s][1][j]);
                }
            }
        }
        #pragma unroll
        for (int s = 0; s < 2; s++)
            #pragma unroll
            for (int k = 0; k < 2; k++) {
                int slot = (qa + (k ? 8 : 0))*36 + s*16 + la3;
                #pragma unroll
                for (int j = 0; j < 3; j++) {
                    float cv, wvr;
                    funpack(accw[s][k][j], cv, wvr);
                    c[s][k][j] = cv;
                    Cq[slot + j] = cv;
                    Ws[l*12 + s*6 + k*3 + j] = -2.f*l1*wvr;
                }
            }
    }
    CPASYNC_WAIT0();
    __syncthreads();   // chunk 0 staged + all C/Ws visible

    int g = 0;         // global chunk counter (0..23)
    for (int step = 0; step < 3; step++) {
        ull acc[2][2][3];   // packed (sum x*gV, sum y*gA); lo initialized to -wv
        #pragma unroll
        for (int s = 0; s < 2; s++)
            #pragma unroll
            for (int k = 0; k < 2; k++)
                #pragma unroll
                for (int j = 0; j < 3; j++)
                    acc[s][k][j] = pack2(Ws[l*12 + s*6 + k*3 + j], 0.f);

        for (int ch = 0; ch < NCHUNK; ch++) {
            char* Fh = FhBase + (g & 1)*FBUF_B;

            // ---- prefetch next chunk into the other buffer (async) ----
            if (g < 3*NCHUNK - 1) {
                int nbase = ((g + 1) & (NCHUNK-1)) * CHK;
                char* dstb = FhBase + ((g + 1) & 1)*FBUF_B;
                const char* srcb = (const char*)(g_Fh + nbase*KN);
                int t = threadIdx.x;
                #pragma unroll
                for (int i = 0; i < 4; i++) {
                    int idx = t + 256*i;
                    int h = idx >> 4, q = idx & 15;
                    cpasync16(dstb + h*ROWB + q*16, srcb + idx*16);
                }
                CPASYNC_COMMIT();
            }

            // ---- Phase A: forward (V,A) for 2 samples + elementwise grads ----
            {
                const char* r0 = Fh + l*ROWB;
                const char* r1 = Fh + (l+32)*ROWB;
                ull va[2][2][3] = {{{0,0,0},{0,0,0}},{{0,0,0},{0,0,0}}};
                #pragma unroll 2
                for (int q = 0; q < 16; q++) {
                    ulonglong2 u0 = *(const ulonglong2*)(r0 + q*16);
                    ulonglong2 u1 = *(const ulonglong2*)(r1 + q*16);
                    ull x0[4], x1[4];
                    x0[0] = h2f2((unsigned)u0.x); x0[1] = h2f2((unsigned)(u0.x >> 32));
                    x0[2] = h2f2((unsigned)u0.y); x0[3] = h2f2((unsigned)(u0.y >> 32));
                    x1[0] = h2f2((unsigned)u1.x); x1[1] = h2f2((unsigned)(u1.x >> 32));
                    x1[2] = h2f2((unsigned)u1.y); x1[3] = h2f2((unsigned)(u1.y >> 32));
                    const float* cqp = Cq + q*36;
                    #pragma unroll
                    for (int s = 0; s < 2; s++) {
                        float4 c0 = *(const float4*)(cqp + s*16);
                        float4 c1 = *(const float4*)(cqp + s*16 + 4);
                        float4 c2 = *(const float4*)(cqp + s*16 + 8);
                        float cf[12] = {c0.x,c0.y,c0.z,c0.w,
                                        c1.x,c1.y,c1.z,c1.w,
                                        c2.x,c2.y,c2.z,c2.w};
                        #pragma unroll
                        for (int i = 0; i < 4; i++) {
                            ull d0 = fdup(cf[i*3+0]);
                            ull d1 = fdup(cf[i*3+1]);
                            ull d2 = fdup(cf[i*3+2]);
                            va[s][0][0] = ffma2(x0[i], d0, va[s][0][0]);
                            va[s][0][1] = ffma2(x0[i], d1, va[s][0][1]);
                            va[s][0][2] = ffma2(x0[i], d2, va[s][0][2]);
                            va[s][1][0] = ffma2(x1[i], d0, va[s][1][0]);
                            va[s][1][1] = ffma2(x1[i], d1, va[s][1][1]);
                            va[s][1][2] = ffma2(x1[i], d2, va[s][1][2]);
                        }
                    }
                }
                float V[3], A[3], gg[6];
                #pragma unroll
                for (int s = 0; s < 2; s++) {
                    float2* Gw = s ? GwB : GwA;
                    float aa = s ? aaB : aaA;
                    float bb = s ? bbB : bbA;
                    #pragma unroll
                    for (int r = 0; r < 2; r++) {
                        funpack(va[s][r][0], V[0], A[0]);
                        funpack(va[s][r][1], V[1], A[1]);
                        funpack(va[s][r][2], V[2], A[2]);
                        elemgrad(V[0],V[1],V[2], A[0],A[1],A[2], aa,bb,l2, gg);
                        int hh = l + 32*r;
                        #pragma unroll
                        for (int j = 0; j < 3; j++)
                            Gw[j*CHK + hh] = make_float2(gg[j], gg[3+j]);
                    }
                }
            }
            __syncwarp();

            // ---- Phase B: dC accumulation (fp16 column reads of the same tile) ----
            {
                const ulonglong2* pgA0 = (const ulonglong2*)(GwA);
                const ulonglong2* pgA1 = (const ulonglong2*)(GwA + CHK);
                const ulonglong2* pgA2 = (const ulonglong2*)(GwA + 2*CHK);
                const ulonglong2* pgB0 = (const ulonglong2*)(GwB);
                const ulonglong2* pgB1 = (const ulonglong2*)(GwB + CHK);
                const ulonglong2* pgB2 = (const ulonglong2*)(GwB + 2*CHK);
                #pragma unroll 2
                for (int hp = 0; hp < 32; hp++) {
                    const char* rowA = Fh + (2*hp)*ROWB;
                    const char* rowB = Fh + (2*hp+1)*ROWB;
                    ull t00 = h2f2(*(const unsigned*)(rowA + l*4));
                    ull t01 = h2f2(*(const unsigned*)(rowA + (l+32)*4));
                    ull t10 = h2f2(*(const unsigned*)(rowB + l*4));
                    ull t11 = h2f2(*(const unsigned*)(rowB + (l+32)*4));
                    ulonglong2 p0 = pgA0[hp], p1 = pgA1[hp], p2 = pgA2[hp];
                    acc[0][0][0] = ffma2(t00, p0.x, acc[0][0][0]);
                    acc[0][0][1] = ffma2(t00, p1.x, acc[0][0][1]);
                    acc[0][0][2] = ffma2(t00, p2.x, acc[0][0][2]);
                    acc[0][1][0] = ffma2(t01, p0.x, acc[0][1][0]);
                    acc[0][1][1] = ffma2(t01, p1.x, acc[0][1][1]);
                    acc[0][1][2] = ffma2(t01, p2.x, acc[0][1][2]);
                    acc[0][0][0] = ffma2(t10, p0.y, acc[0][0][0]);
                    acc[0][0][1] = ffma2(t10, p1.y, acc[0][0][1]);
                    acc[0][0][2] = ffma2(t10, p2.y, acc[0][0][2]);
                    acc[0][1][0] = ffma2(t11, p0.y, acc[0][1][0]);
                    acc[0][1][1] = ffma2(t11, p1.y, acc[0][1][1]);
                    acc[0][1][2] = ffma2(t11, p2.y, acc[0][1][2]);
                    ulonglong2 q0 = pgB0[hp], q1 = pgB1[hp], q2 = pgB2[hp];
                    acc[1][0][0] = ffma2(t00, q0.x, acc[1][0][0]);
                    acc[1][0][1] = ffma2(t00, q1.x, acc[1][0][1]);
                    acc[1][0][2] = ffma2(t00, q2.x, acc[1][0][2]);
                    acc[1][1][0] = ffma2(t01, q0.x, acc[1][1][0]);
                    acc[1][1][1] = ffma2(t01, q1.x, acc[1][1][1]);
                    acc[1][1][2] = ffma2(t01, q2.x, acc[1][1][2]);
                    acc[1][0][0] = ffma2(t10, q0.y, acc[1][0][0]);
                    acc[1][0][1] = ffma2(t10, q1.y, acc[1][0][1]);
                    acc[1][0][2] = ffma2(t10, q2.y, acc[1][0][2]);
                    acc[1][1][0] = ffma2(t11, q0.y, acc[1][1][0]);
                    acc[1][1][1] = ffma2(t11, q1.y, acc[1][1][1]);
                    acc[1][1][2] = ffma2(t11, q2.y, acc[1][1][2]);
                }
            }

            CPASYNC_WAIT0();
            __syncthreads();   // next buffer staged; this buffer free for overwrite
            g++;
        }

        // ---- Phase C: mc = M @ C for both samples, then SGD update ----
        ull mca[2][3] = {{0,0,0},{0,0,0}};
        {
            #pragma unroll 2
            for (int q = 0; q < 16; q++) {
                const float* cqp = Cq + q*36;
                float4 a0 = *(const float4*)(cqp);
                float4 a1 = *(const float4*)(cqp + 4);
                float4 a2 = *(const float4*)(cqp + 8);
                float4 b0 = *(const float4*)(cqp + 16);
                float4 b1 = *(const float4*)(cqp + 20);
                float4 b2 = *(const float4*)(cqp + 24);
                float cA[12] = {a0.x,a0.y,a0.z,a0.w, a1.x,a1.y,a1.z,a1.w, a2.x,a2.y,a2.z,a2.w};
                float cB[12] = {b0.x,b0.y,b0.z,b0.w, b1.x,b1.y,b1.z,b1.w, b2.x,b2.y,b2.z,b2.w};
                #pragma unroll
                for (int i = 0; i < 4; i++) {
                    int kk = 4*q + i;
                    ull pm = *(const ull*)&g_Mp[kk*32 + l];
                    mca[0][0] = ffma2(pm, fdup(cA[i*3+0]), mca[0][0]);
                    mca[0][1] = ffma2(pm, fdup(cA[i*3+1]), mca[0][1]);
                    mca[0][2] = ffma2(pm, fdup(cA[i*3+2]), mca[0][2]);
                    mca[1][0] = ffma2(pm, fdup(cB[i*3+0]), mca[1][0]);
                    mca[1][1] = ffma2(pm, fdup(cB[i*3+1]), mca[1][1]);
                    mca[1][2] = ffma2(pm, fdup(cB[i*3+2]), mca[1][2]);
                }
            }
        }
        __syncwarp();   // all lanes done reading C before update
        #pragma unroll
        for (int s = 0; s < 2; s++)
            #pragma unroll
            for (int k = 0; k < 2; k++) {
                int slot = (qa + (k ? 8 : 0))*36 + s*16 + la3;
                #pragma unroll
                for (int j = 0; j < 3; j++) {
                    float dlo, dhi, m0, m1;
                    funpack(acc[s][k][j], dlo, dhi);    // dlo includes -wv
                    funpack(mca[s][j], m0, m1);
                    float m = k ? m1 : m0;
                    c[s][k][j] -= LRATE * (dlo + dhi + m);
                    Cq[slot + j] = c[s][k][j];
                }
            }
        __syncwarp();
    }

    // ---- output (from registers) ----
    #pragma unroll
    for (int s = 0; s < 2; s++) {
        float* op = out + (size_t)(sA + s) * (KN*3);
        #pragma unroll
        for (int j = 0; j < 3; j++) {
            op[k0*3 + j] = c[s][0][j];
            op[k1*3 + j] = c[s][1][j];
        }
    }
}

extern "C" void kernel_launch(void* const* d_in, const int* in_sizes, int n_in,
                              void* d_out, int out_size)
{
    const float* R_U     = (const float*)d_in[0];
    const float* alpha   = (const float*)d_in[1];
    const float* beta    = (const float*)d_in[2];
    const float* lambdas = (const float*)d_in[3];
    const float* B       = (const float*)d_in[4];
    const float* Bd      = (const float*)d_in[5];
    const float* Bdd     = (const float*)d_in[6];
    const float* Bddd    = (const float*)d_in[7];
    const float* Bpinv   = (const float*)d_in[8];

    cudaFuncSetAttribute(inner_opt_kernel,
                         cudaFuncAttributeMaxDynamicSharedMemorySize, SMEM_BYTES);

    prep_kernel<<<192, 256>>>(B, Bd, Bdd, Bddd, Bpinv, lambdas);
    inner_opt_kernel<<<NSAMP/(WARPS*2), 256, SMEM_BYTES>>>(
        R_U, alpha, beta, lambdas, (float*)d_out);
}

// round 10
// speedup vs baseline: 1.0701x; 1.0701x over previous
#include <cuda_runtime.h>
#include <cuda_fp16.h>

typedef unsigned long long ull;

#define HN 512
#define KN 64
#define NSAMP 16384
#define LRATE 0.001f
#define EPSF 1e-8f
#define WARPS 8
#define CHK 64
#define NCHUNK (HN/CHK)
#define FH_H2 68                      // half2 per staged row (272 B); 68%32==4 -> conflict-free LDS.128

// smem layout (float units)
#define FS_FLOATS   (CHK*FH_H2)       // 4352
#define CS_OFF      FS_FLOATS
#define CS_WARP     576               // 16 quads * 36 floats (A at +0, B at +16, pad)
#define GB_OFF      (CS_OFF + WARPS*CS_WARP)
#define GB_WARP     768
#define WV_OFF      (GB_OFF + WARPS*GB_WARP)
#define SMEM_FLOATS (WV_OFF + WARPS*384)
#define SMEM_BYTES  (SMEM_FLOATS*4)   // 72704 B -> 2 CTAs/SM

__device__ __align__(16) unsigned g_Fh[HN*KN];        // [h][k] = half2(Bd, Bdd)
__device__ __align__(16) float4 g_PT4[(HN/2)*KN];     // [hp][k] = (pinv[k][2hp], B[2hp][k], pinv[k][2hp+1], B[2hp+1][k])
__device__ __align__(16) float2 g_Mp[KN*32];          // [kk*32+l] = (M[kk][l], M[kk][l+32])
__device__ __align__(16) float  g_CW[(NSAMP/2)*768];  // per-pair: [q<6][lane][4] = (c, -2*l1*wv) packed

// ---- packed f32x2 helpers ----
__device__ __forceinline__ ull ffma2(ull a, ull b, ull c){
    ull d; asm("fma.rn.f32x2 %0,%1,%2,%3;" : "=l"(d) : "l"(a), "l"(b), "l"(c)); return d;
}
__device__ __forceinline__ void funpack(ull u, float& x, float& y){
    asm("mov.b64 {%0,%1},%2;" : "=f"(x), "=f"(y) : "l"(u));
}
__device__ __forceinline__ ull fdup(float x){
    ull r; asm("mov.b64 %0,{%1,%1};" : "=l"(r) : "f"(x)); return r;
}
__device__ __forceinline__ ull pack2(float lo, float hi){
    ull r; asm("mov.b64 %0,{%1,%2};" : "=l"(r) : "f"(lo), "f"(hi)); return r;
}
// half2 bits -> packed f32x2
__device__ __forceinline__ ull h2f2(unsigned u){
    __half2 h = *(__half2*)&u;
    float2 f = __half22float2(h);
    return pack2(f.x, f.y);
}
// rsqrt on the fma/alu pipes: bit-hack seed + 2 Newton iterations (~4e-6 rel err)
__device__ __forceinline__ float rsqrt_fma(float x){
    float y = __uint_as_float(0x5f3759dfu - (__float_as_uint(x) >> 1));
    y = y * (1.5f - 0.5f*x*y*y);
    y = y * (1.5f - 0.5f*x*y*y);
    return y;
}

// K1: prep (blocks 0..127) + gram (blocks 128..191)
__global__ void prep_kernel(const float* __restrict__ B,
                            const float* __restrict__ Bd,
                            const float* __restrict__ Bdd,
                            const float* __restrict__ Bddd,
                            const float* __restrict__ Bpinv,
                            const float* __restrict__ lambdas)
{
    int bid = blockIdx.x, t = threadIdx.x;
    if (bid < 128) {
        int idx = bid*256 + t;
        __half2 hv = __halves2half2(__float2half(Bd[idx]), __float2half(Bdd[idx]));
        g_Fh[idx] = *(unsigned*)&hv;
        if (idx < (HN/2)*KN) {
            int hp = idx >> 6, k = idx & 63;
            int h0 = 2*hp, h1 = 2*hp + 1;
            g_PT4[idx] = make_float4(Bpinv[k*HN + h0], B[h0*KN + k],
                                     Bpinv[k*HN + h1], B[h1*KN + k]);
        }
    } else {
        __shared__ float pab[4][KN], paj[4][KN], Mrow[KN];
        int kk = bid - 128;
        int k2 = t & 63, part = t >> 6;
        float ab = 0.f, aj = 0.f;
        for (int h = part*128; h < part*128 + 128; h++) {
            ab += B[h*KN + kk]    * B[h*KN + k2];
            aj += Bddd[h*KN + kk] * Bddd[h*KN + k2];
        }
        pab[part][k2] = ab; paj[part][k2] = aj;
        __syncthreads();
        if (t < KN) {
            float sab = pab[0][t]+pab[1][t]+pab[2][t]+pab[3][t];
            float saj = paj[0][t]+paj[1][t]+paj[2][t]+paj[3][t];
            Mrow[t] = 2.f * (lambdas[0]*sab + lambdas[2]*saj);
        }
        __syncthreads();
        if (t < 32) g_Mp[kk*32 + t] = make_float2(Mrow[t], Mrow[t+32]);
    }
}

// K2: init matvecs hoisted out of the main kernel. One warp = 2 samples;
// computes c = Bpinv@r and -2*l1*(B^T r), stores packed per-lane float4s.
__global__ __launch_bounds__(256)
void init_kernel(const float* __restrict__ R_U,
                 const float* __restrict__ lambdas)
{
    const int w = threadIdx.x >> 5;
    const int l = threadIdx.x & 31;
    const int pair = blockIdx.x * WARPS + w;
    const int sA = pair*2, sB = sA + 1;
    const float l1 = lambdas[0];

    ull accw[2][2][3] = {{{0,0,0},{0,0,0}},{{0,0,0},{0,0,0}}};
    const float4* rpA = (const float4*)(R_U + (size_t)sA * (HN*3));
    const float4* rpB = (const float4*)(R_U + (size_t)sB * (HN*3));
    #pragma unroll 1
    for (int q = 0; q < HN/4; q++) {
        ulonglong2 u00 = *(const ulonglong2*)&g_PT4[(2*q  )*KN + l];
        ulonglong2 u01 = *(const ulonglong2*)&g_PT4[(2*q  )*KN + l + 32];
        ulonglong2 u10 = *(const ulonglong2*)&g_PT4[(2*q+1)*KN + l];
        ulonglong2 u11 = *(const ulonglong2*)&g_PT4[(2*q+1)*KN + l + 32];
        #pragma unroll
        for (int s = 0; s < 2; s++) {
            const float4* rp = s ? rpB : rpA;
            float4 r0 = rp[3*q], r1 = rp[3*q+1], r2 = rp[3*q+2];
            float rr[12] = {r0.x,r0.y,r0.z,r0.w, r1.x,r1.y,r1.z,r1.w, r2.x,r2.y,r2.z,r2.w};
            #pragma unroll
            for (int j = 0; j < 3; j++) {
                ull d0 = fdup(rr[j]);
                ull d1 = fdup(rr[3+j]);
                ull d2 = fdup(rr[6+j]);
                ull d3 = fdup(rr[9+j]);
                accw[s][0][j] = ffma2(u00.x, d0, accw[s][0][j]);
                accw[s][0][j] = ffma2(u00.y, d1, accw[s][0][j]);
                accw[s][0][j] = ffma2(u10.x, d2, accw[s][0][j]);
                accw[s][0][j] = ffma2(u10.y, d3, accw[s][0][j]);
                accw[s][1][j] = ffma2(u01.x, d0, accw[s][1][j]);
                accw[s][1][j] = ffma2(u01.y, d1, accw[s][1][j]);
                accw[s][1][j] = ffma2(u11.x, d2, accw[s][1][j]);
                accw[s][1][j] = ffma2(u11.y, d3, accw[s][1][j]);
            }
        }
    }
    float val[24];
    #pragma unroll
    for (int s = 0; s < 2; s++)
        #pragma unroll
        for (int k = 0; k < 2; k++)
            #pragma unroll
            for (int j = 0; j < 3; j++) {
                float cv, wvr;
                funpack(accw[s][k][j], cv, wvr);
                val[s*6 + k*3 + j]      = cv;
                val[12 + s*6 + k*3 + j] = -2.f*l1*wvr;
            }
    float4* cw = (float4*)(g_CW + (size_t)pair*768);
    #pragma unroll
    for (int q = 0; q < 6; q++)
        cw[q*32 + l] = make_float4(val[4*q], val[4*q+1], val[4*q+2], val[4*q+3]);
}

// Elementwise gradient of the power-law term wrt V and A (includes l2).
__device__ __forceinline__ void elemgrad(
    float v0, float v1, float v2,
    float a0, float a1, float a2,
    float aa, float bb, float l2, float* g)
{
    float vsq = v0*v0 + v1*v1 + v2*v2;
    float inv_vn = vsq > 0.f ? rsqrt_fma(vsq) : 0.f;
    float vn  = vsq * inv_vn;
    float vne = vn + EPSF;

    float cx = v1*a2 - v2*a1;
    float cy = v2*a0 - v0*a2;
    float cz = v0*a1 - v1*a0;
    float csq = cx*cx + cy*cy + cz*cz;
    float inv_cn = csq > 0.f ? rsqrtf(csq) : 0.f;
    float cn = csq * inv_cn;

    float inv_den = inv_vn * inv_vn * inv_vn;
    float kappa = cn * inv_den;

    float ks  = fminf(fmaxf(kappa, 1e-4f), 1e4f);
    float lpr = bb * __logf(ks);
    float lp  = fminf(fmaxf(lpr, -10.f), 10.f);
    float traw   = aa * __expf(lp);
    float target = fminf(fmaxf(traw, 1e-6f), 1e6f);

    float u   = vn - target;
    float gvn = 2.f * l2 * u;
    float gt  = (traw > 1e-6f && traw < 1e6f) ? (-2.f * l2 * u) : 0.f;
    float glk = ((lpr > -10.f && lpr < 10.f) ? gt * traw : 0.f) * bb;
    float gk  = (kappa > 1e-4f && kappa < 1e4f) ? glk : 0.f;
    float gcn  = gk * inv_cn;
    float gden = -gk * inv_den;
    gvn += gden * 3.f * vne * vne;

    float scr = gcn * inv_cn;
    float gc0 = scr * cx, gc1 = scr * cy, gc2 = scr * cz;
    float sV = gvn * inv_vn;
    g[0] = sV*v0 + a1*gc2 - a2*gc1;
    g[1] = sV*v1 + a2*gc0 - a0*gc2;
    g[2] = sV*v2 + a0*gc1 - a1*gc0;
    g[3] = gc1*v2 - gc2*v1;
    g[4] = gc2*v0 - gc0*v2;
    g[5] = gc0*v1 - gc1*v0;
}

// K3: main. One warp = 2 samples; one fp16 tile serves forward rows + backward columns.
// Init state loaded from g_CW (precomputed by init_kernel).
__global__ __launch_bounds__(256, 2)
void inner_opt_kernel(const float* __restrict__ alpha,
                      const float* __restrict__ beta,
                      const float* __restrict__ lambdas,
                      float* __restrict__ out)
{
    extern __shared__ __align__(16) float smem[];
    char* Fh = (char*)smem;                                 // [CHK] rows of 272 B (68 half2)
    const int w = threadIdx.x >> 5;
    const int l = threadIdx.x & 31;
    float* Cq  = smem + CS_OFF + w*CS_WARP;                 // [quad][36]: A 12f @+0, B 12f @+16
    float2* GwA = (float2*)(smem + GB_OFF + w*GB_WARP);     // [j][h] (gV,gA)
    float2* GwB = GwA + 192;
    float*  Ws  = smem + WV_OFF + w*384;                    // [lane][12] -wv stash

    const int pair = blockIdx.x * WARPS + w;
    const int sA = pair*2;
    const int sB = sA + 1;
    const int k0 = l, k1 = l + 32;
    const int qa = l >> 2, la3 = (l & 3) * 3;               // C slot coords for k0 (k1: quad+8)

    const float l2 = lambdas[1];
    const float aaA = alpha[sA], bbA = beta[sA];
    const float aaB = alpha[sB], bbB = beta[sB];

    float c[2][2][3];   // [sample][k-half][j] kept in registers across all steps

    // ---- load precomputed (c, -wv) from init_kernel ----
    {
        const float4* cw = (const float4*)(g_CW + (size_t)pair*768);
        float val[24];
        #pragma unroll
        for (int q = 0; q < 6; q++) {
            float4 v = cw[q*32 + l];
            val[4*q+0] = v.x; val[4*q+1] = v.y; val[4*q+2] = v.z; val[4*q+3] = v.w;
        }
        #pragma unroll
        for (int s = 0; s < 2; s++)
            #pragma unroll
            for (int k = 0; k < 2; k++) {
                int slot = (qa + (k ? 8 : 0))*36 + s*16 + la3;
                #pragma unroll
                for (int j = 0; j < 3; j++) {
                    float cv = val[s*6 + k*3 + j];
                    c[s][k][j] = cv;
                    Cq[slot + j] = cv;
                    Ws[l*12 + s*6 + k*3 + j] = val[12 + s*6 + k*3 + j];
                }
            }
        __syncwarp();
    }

    for (int step = 0; step < 3; step++) {
        ull acc[2][2][3];   // packed (sum x*gV, sum y*gA); lo initialized to -wv
        #pragma unroll
        for (int s = 0; s < 2; s++)
            #pragma unroll
            for (int k = 0; k < 2; k++)
                #pragma unroll
                for (int j = 0; j < 3; j++)
                    acc[s][k][j] = pack2(Ws[l*12 + s*6 + k*3 + j], 0.f);

        for (int ch = 0; ch < NCHUNK; ch++) {
            const int base = ch * CHK;
            __syncthreads();   // previous chunk fully consumed by all warps
            {  // stage fp16 tile (16 KB) into padded rows
                const float4* src = (const float4*)(g_Fh + base*KN);
                int t = threadIdx.x;
                #pragma unroll
                for (int i = 0; i < 4; i++) {
                    int idx = t + 256*i;
                    int h = idx >> 4, q = idx & 15;
                    *(float4*)(Fh + h*272 + q*16) = src[idx];
                }
            }
            __syncthreads();

            // ---- Phase A: forward (V,A) for 2 samples + elementwise grads ----
            {
                const char* r0 = Fh + l*272;
                const char* r1 = Fh + (l+32)*272;
                ull va[2][2][3] = {{{0,0,0},{0,0,0}},{{0,0,0},{0,0,0}}};
                #pragma unroll 2
                for (int q = 0; q < 16; q++) {
                    ulonglong2 u0 = *(const ulonglong2*)(r0 + q*16);
                    ulonglong2 u1 = *(const ulonglong2*)(r1 + q*16);
                    ull x0[4], x1[4];
                    x0[0] = h2f2((unsigned)u0.x); x0[1] = h2f2((unsigned)(u0.x >> 32));
                    x0[2] = h2f2((unsigned)u0.y); x0[3] = h2f2((unsigned)(u0.y >> 32));
                    x1[0] = h2f2((unsigned)u1.x); x1[1] = h2f2((unsigned)(u1.x >> 32));
                    x1[2] = h2f2((unsigned)u1.y); x1[3] = h2f2((unsigned)(u1.y >> 32));
                    const float* cqp = Cq + q*36;
                    #pragma unroll
                    for (int s = 0; s < 2; s++) {
                        float4 c0 = *(const float4*)(cqp + s*16);
                        float4 c1 = *(const float4*)(cqp + s*16 + 4);
                        float4 c2 = *(const float4*)(cqp + s*16 + 8);
                        float cf[12] = {c0.x,c0.y,c0.z,c0.w,
                                        c1.x,c1.y,c1.z,c1.w,
                                        c2.x,c2.y,c2.z,c2.w};
                        #pragma unroll
                        for (int i = 0; i < 4; i++) {
                            ull d0 = fdup(cf[i*3+0]);
                            ull d1 = fdup(cf[i*3+1]);
                            ull d2 = fdup(cf[i*3+2]);
                            va[s][0][0] = ffma2(x0[i], d0, va[s][0][0]);
                            va[s][0][1] = ffma2(x0[i], d1, va[s][0][1]);
                            va[s][0][2] = ffma2(x0[i], d2, va[s][0][2]);
                            va[s][1][0] = ffma2(x1[i], d0, va[s][1][0]);
                            va[s][1][1] = ffma2(x1[i], d1, va[s][1][1]);
                            va[s][1][2] = ffma2(x1[i], d2, va[s][1][2]);
                        }
                    }
                }
                float V[3], A[3], g[6];
                #pragma unroll
                for (int s = 0; s < 2; s++) {
                    float2* Gw = s ? GwB : GwA;
                    float aa = s ? aaB : aaA;
                    float bb = s ? bbB : bbA;
                    #pragma unroll
                    for (int r = 0; r < 2; r++) {
                        funpack(va[s][r][0], V[0], A[0]);
                        funpack(va[s][r][1], V[1], A[1]);
                        funpack(va[s][r][2], V[2], A[2]);
                        elemgrad(V[0],V[1],V[2], A[0],A[1],A[2], aa,bb,l2, g);
                        int hh = l + 32*r;
                        #pragma unroll
                        for (int j = 0; j < 3; j++)
                            Gw[j*CHK + hh] = make_float2(g[j], g[3+j]);
                    }
                }
            }
            __syncwarp();

            // ---- Phase B: dC accumulation (fp16 column reads of the same tile) ----
            {
                const ulonglong2* pgA0 = (const ulonglong2*)(GwA);
                const ulonglong2* pgA1 = (const ulonglong2*)(GwA + CHK);
                const ulonglong2* pgA2 = (const ulonglong2*)(GwA + 2*CHK);
                const ulonglong2* pgB0 = (const ulonglong2*)(GwB);
                const ulonglong2* pgB1 = (const ulonglong2*)(GwB + CHK);
                const ulonglong2* pgB2 = (const ulonglong2*)(GwB + 2*CHK);
                #pragma unroll 2
                for (int hp = 0; hp < 32; hp++) {
                    const char* rowA = Fh + (2*hp)*272;
                    const char* rowB = Fh + (2*hp+1)*272;
                    ull t00 = h2f2(*(const unsigned*)(rowA + l*4));
                    ull t01 = h2f2(*(const unsigned*)(rowA + (l+32)*4));
                    ull t10 = h2f2(*(const unsigned*)(rowB + l*4));
                    ull t11 = h2f2(*(const unsigned*)(rowB + (l+32)*4));
                    ulonglong2 p0 = pgA0[hp], p1 = pgA1[hp], p2 = pgA2[hp];
                    acc[0][0][0] = ffma2(t00, p0.x, acc[0][0][0]);
                    acc[0][0][1] = ffma2(t00, p1.x, acc[0][0][1]);
                    acc[0][0][2] = ffma2(t00, p2.x, acc[0][0][2]);
                    acc[0][1][0] = ffma2(t01, p0.x, acc[0][1][0]);
                    acc[0][1][1] = ffma2(t01, p1.x, acc[0][1][1]);
                    acc[0][1][2] = ffma2(t01, p2.x, acc[0][1][2]);
                    acc[0][0][0] = ffma2(t10, p0.y, acc[0][0][0]);
                    acc[0][0][1] = ffma2(t10, p1.y, acc[0][0][1]);
                    acc[0][0][2] = ffma2(t10, p2.y, acc[0][0][2]);
                    acc[0][1][0] = ffma2(t11, p0.y, acc[0][1][0]);
                    acc[0][1][1] = ffma2(t11, p1.y, acc[0][1][1]);
                    acc[0][1][2] = ffma2(t11, p2.y, acc[0][1][2]);
                    ulonglong2 q0 = pgB0[hp], q1 = pgB1[hp], q2 = pgB2[hp];
                    acc[1][0][0] = ffma2(t00, q0.x, acc[1][0][0]);
                    acc[1][0][1] = ffma2(t00, q1.x, acc[1][0][1]);
                    acc[1][0][2] = ffma2(t00, q2.x, acc[1][0][2]);
                    acc[1][1][0] = ffma2(t01, q0.x, acc[1][1][0]);
                    acc[1][1][1] = ffma2(t01, q1.x, acc[1][1][1]);
                    acc[1][1][2] = ffma2(t01, q2.x, acc[1][1][2]);
                    acc[1][0][0] = ffma2(t10, q0.y, acc[1][0][0]);
                    acc[1][0][1] = ffma2(t10, q1.y, acc[1][0][1]);
                    acc[1][0][2] = ffma2(t10, q2.y, acc[1][0][2]);
                    acc[1][1][0] = ffma2(t11, q0.y, acc[1][1][0]);
                    acc[1][1][1] = ffma2(t11, q1.y, acc[1][1][1]);
                    acc[1][1][2] = ffma2(t11, q2.y, acc[1][1][2]);
                }
            }
        }

        // ---- Phase C: mc = M @ C for both samples, then SGD update ----
        ull mca[2][3] = {{0,0,0},{0,0,0}};
        {
            #pragma unroll 2
            for (int q = 0; q < 16; q++) {
                const float* cqp = Cq + q*36;
                float4 a0 = *(const float4*)(cqp);
                float4 a1 = *(const float4*)(cqp + 4);
                float4 a2 = *(const float4*)(cqp + 8);
                float4 b0 = *(const float4*)(cqp + 16);
                float4 b1 = *(const float4*)(cqp + 20);
                float4 b2 = *(const float4*)(cqp + 24);
                float cA[12] = {a0.x,a0.y,a0.z,a0.w, a1.x,a1.y,a1.z,a1.w, a2.x,a2.y,a2.z,a2.w};
                float cB[12] = {b0.x,b0.y,b0.z,b0.w, b1.x,b1.y,b1.z,b1.w, b2.x,b2.y,b2.z,b2.w};
                #pragma unroll
                for (int i = 0; i < 4; i++) {
                    int kk = 4*q + i;
                    ull pm = *(const ull*)&g_Mp[kk*32 + l];
                    mca[0][0] = ffma2(pm, fdup(cA[i*3+0]), mca[0][0]);
                    mca[0][1] = ffma2(pm, fdup(cA[i*3+1]), mca[0][1]);
                    mca[0][2] = ffma2(pm, fdup(cA[i*3+2]), mca[0][2]);
                    mca[1][0] = ffma2(pm, fdup(cB[i*3+0]), mca[1][0]);
                    mca[1][1] = ffma2(pm, fdup(cB[i*3+1]), mca[1][1]);
                    mca[1][2] = ffma2(pm, fdup(cB[i*3+2]), mca[1][2]);
                }
            }
        }
        __syncwarp();   // all lanes done reading C before update
        #pragma unroll
        for (int s = 0; s < 2; s++)
            #pragma unroll
            for (int k = 0; k < 2; k++) {
                int slot = (qa + (k ? 8 : 0))*36 + s*16 + la3;
                #pragma unroll
                for (int j = 0; j < 3; j++) {
                    float dlo, dhi, m0, m1;
                    funpack(acc[s][k][j], dlo, dhi);    // dlo includes -wv
                    funpack(mca[s][j], m0, m1);
                    float m = k ? m1 : m0;
                    c[s][k][j] -= LRATE * (dlo + dhi + m);
                    Cq[slot + j] = c[s][k][j];
                }
            }
        __syncwarp();
    }

    // ---- output (from registers) ----
    #pragma unroll
    for (int s = 0; s < 2; s++) {
        float* op = out + (size_t)(sA + s) * (KN*3);
        #pragma unroll
        for (int j = 0; j < 3; j++) {
            op[k0*3 + j] = c[s][0][j];
            op[k1*3 + j] = c[s][1][j];
        }
    }
}

extern "C" void kernel_launch(void* const* d_in, const int* in_sizes, int n_in,
                              void* d_out, int out_size)
{
    const float* R_U     = (const float*)d_in[0];
    const float* alpha   = (const float*)d_in[1];
    const float* beta    = (const float*)d_in[2];
    const float* lambdas = (const float*)d_in[3];
    const float* B       = (const float*)d_in[4];
    const float* Bd      = (const float*)d_in[5];
    const float* Bdd     = (const float*)d_in[6];
    const float* Bddd    = (const float*)d_in[7];
    const float* Bpinv   = (const float*)d_in[8];

    cudaFuncSetAttribute(inner_opt_kernel,
                         cudaFuncAttributeMaxDynamicSharedMemorySize, SMEM_BYTES);

    prep_kernel<<<192, 256>>>(B, Bd, Bdd, Bddd, Bpinv, lambdas);
    init_kernel<<<NSAMP/(WARPS*2), 256>>>(R_U, lambdas);
    inner_opt_kernel<<<NSAMP/(WARPS*2), 256, SMEM_BYTES>>>(
        alpha, beta, lambdas, (float*)d_out);
}